// round 8
// baseline (speedup 1.0000x reference)
#include <cuda_runtime.h>
#include <math.h>

// ---------------------------------------------------------------------------
// Problem constants
// ---------------------------------------------------------------------------
#define NB   64
#define TT   800
#define HH   512
#define H2   1024
#define H3   3072   // 3*H2
#define H4   2048   // 4*H
#define OO   80
#define RR   2

#define NGRID 444      // 3 CTAs/SM worth; 4/SM resident capacity -> all co-resident
#define NT    128
#define CH    32
#define NCHUNK (TT / CH)   // 25

typedef unsigned long long ull;

// ---------------------------------------------------------------------------
// Scratch
// ---------------------------------------------------------------------------
#define GSZ (NB * H3)
#define OFF_GI_ATT   0
#define OFF_GH_ATT   (1 * GSZ)
#define OFF_GI_D1    (2 * GSZ)
#define OFF_GH_D1    (3 * GSZ)
#define OFF_GI_D2    (4 * GSZ)
#define OFF_GH_D2    (5 * GSZ)
#define OFF_PRE_A    (6 * GSZ)
#define OFF_PRE      (OFF_PRE_A   + NB * H2)
#define OFF_DP       (OFF_PRE     + NB * HH)
#define OFF_RESID_SC (OFF_DP      + NB * H2)
#define OFF_RESID    (OFF_RESID_SC+ NB * H2)
#define OFF_RESID2   (OFF_RESID   + NB * H2)
#define OFF_DECIN    (OFF_RESID2  + NB * H2)
#define OFF_SSUM     (OFF_DECIN   + NB * H4)
#define OFF_FLAGS    (OFF_SSUM    + 64)     // 48 ints (slice flags)
#define OFF_HATT     (OFF_FLAGS   + 64)
#define OFF_HD1      (OFF_HATT    + NB * H2)
#define OFF_HD2      (OFF_HD1     + NB * H2)
#define SCRATCH_TOTAL (OFF_HD2    + NB * H2)

__device__ __align__(256) float g_scratch[SCRATCH_TOTAL];
__device__ unsigned g_bar[16];   // monotonic epoch barriers (never reset)

// ---------------------------------------------------------------------------
// Math helpers
// ---------------------------------------------------------------------------
__device__ __forceinline__ float fast_tanh(float x) {
    float e = __expf(2.0f * x);
    return 1.0f - 2.0f / (e + 1.0f);
}
__device__ __forceinline__ float approx_tanh(float x) {
    float y;
    asm("tanh.approx.f32 %0, %1;" : "=f"(y) : "f"(x));
    return y;
}
__device__ __forceinline__ float fast_sigmoid(float x) {
    return 1.0f / (1.0f + __expf(-x));
}
__device__ __forceinline__ ull pk2(float x, float y) {
    ull r;
    asm("mov.b64 %0, {%1, %2};" : "=l"(r) : "f"(x), "f"(y));
    return r;
}
__device__ __forceinline__ void upk2(ull v, float& x, float& y) {
    asm("mov.b64 {%0, %1}, %2;" : "=f"(x), "=f"(y) : "l"(v));
}
__device__ __forceinline__ void ffma2(ull& d, ull a, ull b) {
    asm("fma.rn.f32x2 %0, %1, %2, %0;" : "+l"(d) : "l"(a), "l"(b));
}
__device__ __forceinline__ void red4(float* p, float x, float y, float z, float w) {
    asm volatile("red.global.add.v4.f32 [%0], {%1,%2,%3,%4};"
                 :: "l"(p), "f"(x), "f"(y), "f"(z), "f"(w) : "memory");
}

// ---------------------------------------------------------------------------
// Device-wide barrier: monotonic epoch counter, release/acquire, replay-safe.
// All NGRID CTAs are guaranteed co-resident (see launch_bounds + grid sizing).
// ---------------------------------------------------------------------------
__device__ __forceinline__ void gsync(int id) {
    __syncthreads();
    if (threadIdx.x == 0) {
        unsigned* p = &g_bar[id];
        unsigned old;
        asm volatile("atom.release.gpu.add.u32 %0, [%1], 1;"
                     : "=r"(old) : "l"(p) : "memory");
        unsigned target = (old / NGRID) * NGRID + NGRID;
        unsigned cur;
        do {
            asm volatile("ld.acquire.gpu.u32 %0, [%1];"
                         : "=r"(cur) : "l"(p) : "memory");
            if (cur >= target) break;
            __nanosleep(64);
        } while (true);
    }
    __syncthreads();
}

// ---------------------------------------------------------------------------
// Kernel parameters
// ---------------------------------------------------------------------------
struct KParams {
    const float *input_enc, *attW_enc, *input_dec;
    const int* lengths;
    const float *hidden_att, *hidden_dec1, *hidden_dec2;
    const float *W_pre1, *b_pre1, *W_pre2, *b_pre2;
    const float *Wih_att, *Whh_att, *bih_att, *bhh_att;
    const float *W_ld, *b_ld, *W_attn, *b_attn, *W_sc, *b_sc;
    const float *Wih_d1, *Whh_d1, *bih_d1, *bhh_d1;
    const float *Wih_d2, *Whh_d2, *bih_d2, *bhh_d2;
    const float *W_out, *b_out;
    float *out, *h_att_out, *h_d1_out, *h_d2_out;
};

// ---------------------------------------------------------------------------
// GEMM descriptor (64x64 tile, 128 threads, split-K, red.v4 epilogue)
// mode: 0 identity, 1 relu(A), 2 divide cols k<1024 by ssum[row]
// slices: 16 per-slice nonzero flags; if all zero, A==0 -> skip block
// ---------------------------------------------------------------------------
struct GD {
    const float* A; const float* W; float* C;
    const float* ssum; const int* slices;
    int lda, M, K, KS, inner, mode, nCol, start, nBlocks;
};

__device__ __forceinline__ GD mk(const float* A, int lda, int mode, const float* W,
                                 float* C, int M, int K, int KS, int inner,
                                 const float* ssum, const int* slices) {
    GD d;
    d.A = A; d.W = W; d.C = C; d.ssum = ssum; d.slices = slices;
    d.lda = lda; d.M = M; d.K = K; d.KS = KS; d.inner = inner; d.mode = mode;
    d.nCol = (M + 63) >> 6; d.start = 0; d.nBlocks = d.nCol * (K / KS);
    return d;
}

__device__ __noinline__ void gemm_stage(const GD* P, int n, float* As, float* Ws) {
    int total = P[n - 1].start + P[n - 1].nBlocks;
    int tid = threadIdx.x;
    int ty = tid >> 4;
    int tx = tid & 15;
    int arow = tid & 63;
    int half = tid >> 6;
    int wcol = tid & 63;
    const float4 z4 = make_float4(0.f, 0.f, 0.f, 0.f);

    for (int b = blockIdx.x; b < total; b += NGRID) {
        GD d = P[0];
        for (int i = 1; i < n; i++)
            if (b >= P[i].start) d = P[i];
        if (d.slices) {
            int s = 0;
#pragma unroll
            for (int i = 0; i < 16; i++) s |= d.slices[i];
            if (s == 0) continue;
        }
        int lb = b - d.start;
        int colBlock = lb % d.nCol;
        int kBlock = lb / d.nCol;
        int colBase = colBlock * 64;
        int k0 = kBlock * d.KS;
        int gc = colBase + wcol;
        bool wvalid = (gc < d.M);

        float wv = 1.0f;
        if (d.mode == 2) wv = 1.0f / fmaxf(d.ssum[arow], 1e-12f);

        const float* aptr = d.A + (size_t)arow * d.lda;
        const float* wptr = d.W + (size_t)(wvalid ? gc : 0) * d.K;

        ull acc[4][4];
#pragma unroll
        for (int p = 0; p < 4; p++)
#pragma unroll
            for (int j = 0; j < 4; j++) acc[p][j] = pk2(0.0f, 0.0f);

        int nref = d.KS / d.inner;
        int hk = d.inner >> 1;
        int nf4 = hk >> 2;

        float4 aq[4], wq[4];
#pragma unroll
        for (int q = 0; q < 4; q++) {
            if (q < nf4) {
                int kl = half * hk + q * 4;
                aq[q] = *(const float4*)(aptr + k0 + kl);
                wq[q] = wvalid ? *(const float4*)(wptr + k0 + kl) : z4;
            }
        }

        int kb = k0;
        for (int rf = 0; rf < nref; rf++) {
#pragma unroll
            for (int q = 0; q < 4; q++) {
                if (q < nf4) {
                    int kl = half * hk + q * 4;
                    float4 v = aq[q];
                    if (d.mode == 1) {
                        v.x = fmaxf(v.x, 0.f); v.y = fmaxf(v.y, 0.f);
                        v.z = fmaxf(v.z, 0.f); v.w = fmaxf(v.w, 0.f);
                    } else if (d.mode == 2 && (kb + kl) < H2) {
                        v.x *= wv; v.y *= wv; v.z *= wv; v.w *= wv;
                    }
                    As[(kl + 0) * 64 + arow] = v.x; As[(kl + 1) * 64 + arow] = v.y;
                    As[(kl + 2) * 64 + arow] = v.z; As[(kl + 3) * 64 + arow] = v.w;
                    float4 u = wq[q];
                    Ws[(kl + 0) * 64 + wcol] = u.x; Ws[(kl + 1) * 64 + wcol] = u.y;
                    Ws[(kl + 2) * 64 + wcol] = u.z; Ws[(kl + 3) * 64 + wcol] = u.w;
                }
            }
            __syncthreads();

            if (rf + 1 < nref) {
                int kn = kb + d.inner;
#pragma unroll
                for (int q = 0; q < 4; q++) {
                    if (q < nf4) {
                        int kl = half * hk + q * 4;
                        aq[q] = *(const float4*)(aptr + kn + kl);
                        wq[q] = wvalid ? *(const float4*)(wptr + kn + kl) : z4;
                    }
                }
            }

#pragma unroll 4
            for (int kk = 0; kk < d.inner; kk++) {
                const float* ab = &As[kk * 64 + ty * 8];
                ulonglong2 Ap0 = *(const ulonglong2*)(ab);
                ulonglong2 Ap1 = *(const ulonglong2*)(ab + 4);
                float4 bv = *(const float4*)&Ws[kk * 64 + tx * 4];
                ull b0 = pk2(bv.x, bv.x);
                ull b1 = pk2(bv.y, bv.y);
                ull b2 = pk2(bv.z, bv.z);
                ull b3 = pk2(bv.w, bv.w);
                ffma2(acc[0][0], Ap0.x, b0); ffma2(acc[0][1], Ap0.x, b1);
                ffma2(acc[0][2], Ap0.x, b2); ffma2(acc[0][3], Ap0.x, b3);
                ffma2(acc[1][0], Ap0.y, b0); ffma2(acc[1][1], Ap0.y, b1);
                ffma2(acc[1][2], Ap0.y, b2); ffma2(acc[1][3], Ap0.y, b3);
                ffma2(acc[2][0], Ap1.x, b0); ffma2(acc[2][1], Ap1.x, b1);
                ffma2(acc[2][2], Ap1.x, b2); ffma2(acc[2][3], Ap1.x, b3);
                ffma2(acc[3][0], Ap1.y, b0); ffma2(acc[3][1], Ap1.y, b1);
                ffma2(acc[3][2], Ap1.y, b2); ffma2(acc[3][3], Ap1.y, b3);
            }
            __syncthreads();
            kb += d.inner;
        }

        int col = colBase + tx * 4;
        if (col < d.M) {
#pragma unroll
            for (int p = 0; p < 4; p++) {
                int r0 = ty * 8 + 2 * p;
                float lo0, hi0, lo1, hi1, lo2, hi2, lo3, hi3;
                upk2(acc[p][0], lo0, hi0);
                upk2(acc[p][1], lo1, hi1);
                upk2(acc[p][2], lo2, hi2);
                upk2(acc[p][3], lo3, hi3);
                red4(&d.C[(size_t)r0 * d.M + col], lo0, lo1, lo2, lo3);
                red4(&d.C[(size_t)(r0 + 1) * d.M + col], hi0, hi1, hi2, hi3);
            }
        }
    }
}

// ---------------------------------------------------------------------------
// GRU combine (grid-stride)
// ---------------------------------------------------------------------------
__device__ __noinline__ void combine_stage(const float* gi, const float* gh,
        const float* bih, const float* bhh, const float* hprev,
        float* hout, const float* extra_in, float* extra_out, int mode) {
    for (int idx = blockIdx.x * NT + threadIdx.x; idx < NB * H2; idx += NGRID * NT) {
        int n = idx >> 10;
        int j = idx & (H2 - 1);
        const float* gin = gi + (size_t)n * H3;
        const float* ghn = gh + (size_t)n * H3;
        float ir = gin[j]           + bih[j];
        float iz = gin[j + H2]      + bih[j + H2];
        float in_ = gin[j + 2 * H2] + bih[j + 2 * H2];
        float hr = ghn[j]           + bhh[j];
        float hz = ghn[j + H2]      + bhh[j + H2];
        float hn = ghn[j + 2 * H2]  + bhh[j + 2 * H2];
        float r = fast_sigmoid(ir + hr);
        float z = fast_sigmoid(iz + hz);
        float nn = fast_tanh(in_ + r * hn);
        float h = (1.0f - z) * nn + z * hprev[idx];
        hout[idx] = h;
        if (mode == 1) {
            extra_out[(size_t)n * H4 + H2 + j] = h;
        } else if (mode == 2) {
            extra_out[idx] = extra_in[idx] + h;
        }
    }
}

// ---------------------------------------------------------------------------
// Fused attention (item loop over (n, chunk); 128 threads)
// ---------------------------------------------------------------------------
__device__ __noinline__ void attn_stage(const float* attW, const float* enc,
        const float* dp, const float* Wattn, const float* battn,
        const int* lengths, float* dec_in, float* ssum, float* sh) {
    float* dps = sh;
    float* was = sh + 1024;
    float* ss  = sh + 2048;   // 32
    int tid = threadIdx.x;
    int warp = tid >> 5, lane = tid & 31;

    for (int item = blockIdx.x; item < NB * NCHUNK; item += NGRID) {
        int n = item / NCHUNK;
        int c = item - n * NCHUNK;
        int t0 = c * CH;
        int len = lengths[n];
        if (t0 >= len) continue;
        int kmax = min(CH, len - t0);

        __syncthreads();   // previous item done with smem
        for (int i = tid; i < H2; i += NT) {
            dps[i] = dp[(size_t)n * H2 + i];
            was[i] = Wattn[i];
        }
        if (tid < CH) ss[tid] = 0.0f;
        __syncthreads();

        float bb = battn[0];
#pragma unroll
        for (int rep = 0; rep < 8; rep++) {
            int lt = warp * 8 + rep;
            if (lt < kmax) {
                const float4* row = (const float4*)(attW + ((size_t)n * TT + t0 + lt) * H2);
                const float4* d4 = (const float4*)dps;
                const float4* w4 = (const float4*)was;
                float s = 0.0f;
#pragma unroll
                for (int it = 0; it < 8; it++) {
                    int i = it * 32 + lane;
                    float4 v = row[i];
                    float4 dd = d4[i];
                    float4 ww = w4[i];
                    s += approx_tanh(v.x + dd.x) * ww.x
                       + approx_tanh(v.y + dd.y) * ww.y
                       + approx_tanh(v.z + dd.z) * ww.z
                       + approx_tanh(v.w + dd.w) * ww.w;
                }
#pragma unroll
                for (int o = 16; o; o >>= 1) s += __shfl_xor_sync(0xffffffffu, s, o);
                if (lane == 0) ss[lt] = __expf(s + bb);
            }
        }
        __syncthreads();

        if (warp == 0) {
            float v = ss[lane];
#pragma unroll
            for (int o = 16; o; o >>= 1) v += __shfl_xor_sync(0xffffffffu, v, o);
            if (lane == 0) atomicAdd(&ssum[n], v);
        }

        int h = tid * 4;
        const float* eb = enc + ((size_t)n * TT + t0) * H2;
        float a0 = 0.f, a1 = 0.f, a2 = 0.f, a3 = 0.f;
        float c0 = 0.f, c1 = 0.f, c2 = 0.f, c3 = 0.f;
#pragma unroll 4
        for (int t = 0; t < kmax; t++) {
            float w = ss[t];
            float4 e0 = *(const float4*)(eb + (size_t)t * H2 + h);
            float4 e1 = *(const float4*)(eb + (size_t)t * H2 + h + 512);
            a0 += w * e0.x; a1 += w * e0.y; a2 += w * e0.z; a3 += w * e0.w;
            c0 += w * e1.x; c1 += w * e1.y; c2 += w * e1.z; c3 += w * e1.w;
        }
        red4(&dec_in[(size_t)n * H4 + h], a0, a1, a2, a3);
        red4(&dec_in[(size_t)n * H4 + h + 512], c0, c1, c2, c3);
    }
}

// ---------------------------------------------------------------------------
// Init stage: flag slices + zeroing + bias broadcasts
// ---------------------------------------------------------------------------
__device__ __noinline__ void init_stage(const KParams& p) {
    // flag slices: blocks 0..47, race-free (one writer per slot)
    if (blockIdx.x < 48) {
        int buf = blockIdx.x >> 4, s = blockIdx.x & 15;
        const float* hsrc = (buf == 0) ? p.hidden_att
                          : (buf == 1) ? p.hidden_dec1 : p.hidden_dec2;
        const float* base = hsrc + s * 4096;
        int any = 0;
        for (int i = threadIdx.x; i < 4096; i += NT) any |= (base[i] != 0.0f);
        int r = __syncthreads_or(any);
        if (threadIdx.x == 0)
            ((int*)(g_scratch + OFF_FLAGS))[blockIdx.x] = r;
    }
    int gtid = blockIdx.x * NT + threadIdx.x;
    // vectorized zero of 6 gate buffers
    float4 z4 = make_float4(0.f, 0.f, 0.f, 0.f);
    float4* g4 = (float4*)g_scratch;
    for (int i = gtid; i < (6 * GSZ) / 4; i += NGRID * NT) g4[i] = z4;
    // bias broadcasts + dec_in first-half zero
    for (int i = gtid; i < NB * H2; i += NGRID * NT) {
        int j = i & (H2 - 1);
        g_scratch[OFF_PRE_A + i]    = p.b_pre1[j];
        g_scratch[OFF_DP + i]       = p.b_ld[j];
        g_scratch[OFF_RESID_SC + i] = p.b_sc[j];
        int n = i >> 10;
        g_scratch[OFF_DECIN + (size_t)n * H4 + j] = 0.0f;
    }
    for (int i = gtid; i < NB * HH; i += NGRID * NT)
        g_scratch[OFF_PRE + i] = p.b_pre2[i & (HH - 1)];
    for (int i = gtid; i < NB * RR * OO; i += NGRID * NT)
        p.out[i] = p.b_out[i % (RR * OO)];
    if (gtid < 64) g_scratch[OFF_SSUM + gtid] = 0.0f;
}

// ---------------------------------------------------------------------------
// The persistent mega kernel
// ---------------------------------------------------------------------------
__global__ __launch_bounds__(NT, 4) void mega_kernel(KParams p) {
    __shared__ float sbuf[4160];
    float* As = sbuf;
    float* Ws = sbuf + 2048;

    float* gi_att = g_scratch + OFF_GI_ATT;
    float* gh_att = g_scratch + OFF_GH_ATT;
    float* gi_d1  = g_scratch + OFF_GI_D1;
    float* gh_d1  = g_scratch + OFF_GH_D1;
    float* gi_d2  = g_scratch + OFF_GI_D2;
    float* gh_d2  = g_scratch + OFF_GH_D2;
    float* pre_a  = g_scratch + OFF_PRE_A;
    float* pre    = g_scratch + OFF_PRE;
    float* dp     = g_scratch + OFF_DP;
    float* resid_sc = g_scratch + OFF_RESID_SC;
    float* resid  = g_scratch + OFF_RESID;
    float* resid2 = g_scratch + OFF_RESID2;
    float* dec_in = g_scratch + OFF_DECIN;
    float* ssum   = g_scratch + OFF_SSUM;
    const int* fl = (const int*)(g_scratch + OFF_FLAGS);

    // s0: init + flags
    init_stage(p);
    gsync(0);

    // s1: pre_a + (gh_att, gh_d1, gh_d2 — skipped when hidden == 0)
    {
        GD ds[4] = {
            mk(p.input_dec,   OO, 0, p.W_pre1,  pre_a,  H2, OO,   16, 16, 0, 0),
            mk(p.hidden_att,  H2, 0, p.Whh_att, gh_att, H3, H2,  256, 32, 0, fl + 0),
            mk(p.hidden_dec1, H2, 0, p.Whh_d1,  gh_d1,  H3, H2,  256, 32, 0, fl + 16),
            mk(p.hidden_dec2, H2, 0, p.Whh_d2,  gh_d2,  H3, H2,  256, 32, 0, fl + 32),
        };
        int st = 0;
        for (int i = 0; i < 4; i++) { ds[i].start = st; st += ds[i].nBlocks; }
        gemm_stage(ds, 4, As, Ws);
    }
    gsync(1);

    // s2: pre = relu(pre_a) @ W_pre2^T + b2
    {
        GD ds[1] = { mk(pre_a, H2, 1, p.W_pre2, pre, HH, H2, 32, 32, 0, 0) };
        gemm_stage(ds, 1, As, Ws);
    }
    gsync(2);

    // s3: gi_att = relu(pre) @ Wih_att^T
    {
        GD ds[1] = { mk(pre, HH, 1, p.Wih_att, gi_att, H3, HH, 64, 32, 0, 0) };
        gemm_stage(ds, 1, As, Ws);
    }
    gsync(3);

    // s4: h_att (also writes dec_in[:, 1024:2048])
    combine_stage(gi_att, gh_att, p.bih_att, p.bhh_att, p.hidden_att,
                  p.h_att_out, 0, dec_in, 1);
    gsync(4);

    // s5: dec_proj
    {
        GD ds[1] = { mk(p.h_att_out, H2, 0, p.W_ld, dp, H2, H2, 64, 32, 0, 0) };
        gemm_stage(ds, 1, As, Ws);
    }
    gsync(5);

    // s6: fused attention
    attn_stage(p.attW_enc, p.input_enc, dp, p.W_attn, p.b_attn, p.lengths,
               dec_in, ssum, sbuf);
    gsync(6);

    // s7: short-cut + gi_d1 (mode 2 normalizes attn half of dec_in on load)
    {
        GD ds[2] = {
            mk(dec_in, H4, 2, p.W_sc,   resid_sc, H2, H4, 128, 32, ssum, 0),
            mk(dec_in, H4, 2, p.Wih_d1, gi_d1,    H3, H4, 128, 32, ssum, 0),
        };
        int st = 0;
        for (int i = 0; i < 2; i++) { ds[i].start = st; st += ds[i].nBlocks; }
        gemm_stage(ds, 2, As, Ws);
    }
    gsync(7);

    // s8: h_dec1 + residual
    combine_stage(gi_d1, gh_d1, p.bih_d1, p.bhh_d1, p.hidden_dec1,
                  p.h_d1_out, resid_sc, resid, 2);
    gsync(8);

    // s9: gi_d2
    {
        GD ds[1] = { mk(resid, H2, 0, p.Wih_d2, gi_d2, H3, H2, 128, 32, 0, 0) };
        gemm_stage(ds, 1, As, Ws);
    }
    gsync(9);

    // s10: h_dec2 + residual2
    combine_stage(gi_d2, gh_d2, p.bih_d2, p.bhh_d2, p.hidden_dec2,
                  p.h_d2_out, resid, resid2, 2);
    gsync(10);

    // s11: output projection into bias-initialized d_out
    {
        GD ds[1] = { mk(resid2, H2, 0, p.W_out, p.out, RR * OO, H2, 16, 16, 0, 0) };
        gemm_stage(ds, 1, As, Ws);
    }
}

// ---------------------------------------------------------------------------
// Host launch: ONE kernel
// ---------------------------------------------------------------------------
extern "C" void kernel_launch(void* const* d_in, const int* in_sizes, int n_in,
                              void* d_out, int out_size) {
    KParams p;
    p.input_enc   = (const float*)d_in[0];
    p.attW_enc    = (const float*)d_in[1];
    p.input_dec   = (const float*)d_in[2];
    p.lengths     = (const int*)  d_in[3];
    p.hidden_att  = (const float*)d_in[4];
    p.hidden_dec1 = (const float*)d_in[5];
    p.hidden_dec2 = (const float*)d_in[6];
    p.W_pre1 = (const float*)d_in[7];   p.b_pre1 = (const float*)d_in[8];
    p.W_pre2 = (const float*)d_in[9];   p.b_pre2 = (const float*)d_in[10];
    p.Wih_att = (const float*)d_in[11]; p.Whh_att = (const float*)d_in[12];
    p.bih_att = (const float*)d_in[13]; p.bhh_att = (const float*)d_in[14];
    p.W_ld  = (const float*)d_in[15];   p.b_ld  = (const float*)d_in[16];
    p.W_attn = (const float*)d_in[17];  p.b_attn = (const float*)d_in[18];
    p.W_sc  = (const float*)d_in[19];   p.b_sc  = (const float*)d_in[20];
    p.Wih_d1 = (const float*)d_in[21];  p.Whh_d1 = (const float*)d_in[22];
    p.bih_d1 = (const float*)d_in[23];  p.bhh_d1 = (const float*)d_in[24];
    p.Wih_d2 = (const float*)d_in[25];  p.Whh_d2 = (const float*)d_in[26];
    p.bih_d2 = (const float*)d_in[27];  p.bhh_d2 = (const float*)d_in[28];
    p.W_out = (const float*)d_in[29];   p.b_out = (const float*)d_in[30];

    float* out = (float*)d_out;
    p.out = out;

    float* sc = nullptr;
    cudaGetSymbolAddress((void**)&sc, g_scratch);

    bool full_out = (out_size >= NB * RR * OO + 3 * NB * H2);
    p.h_att_out = full_out ? out + NB * RR * OO : sc + OFF_HATT;
    p.h_d1_out  = full_out ? p.h_att_out + NB * H2 : sc + OFF_HD1;
    p.h_d2_out  = full_out ? p.h_d1_out + NB * H2 : sc + OFF_HD2;

    mega_kernel<<<NGRID, NT>>>(p);
}

// round 11
// speedup vs baseline: 1.0550x; 1.0550x over previous
#include <cuda_runtime.h>
#include <math.h>

// ---------------------------------------------------------------------------
// Problem constants
// ---------------------------------------------------------------------------
#define NB   64
#define TT   800
#define HH   512
#define H2   1024
#define H3   3072   // 3*H2
#define H4   2048   // 4*H
#define OO   80
#define RR   2

#define NGRID 444
#define NT    128
#define CH    32
#define NCHUNK (TT / CH)   // 25

typedef unsigned long long ull;

// ---------------------------------------------------------------------------
// Scratch
// ---------------------------------------------------------------------------
#define GSZ (NB * H3)
#define OFF_GI_ATT   0
#define OFF_GH_ATT   (1 * GSZ)
#define OFF_GI_D1    (2 * GSZ)
#define OFF_GH_D1    (3 * GSZ)
#define OFF_GI_D2    (4 * GSZ)
#define OFF_GH_D2    (5 * GSZ)
#define OFF_PRE_A    (6 * GSZ)
#define OFF_PRE      (OFF_PRE_A   + NB * H2)
#define OFF_DP       (OFF_PRE     + NB * HH)
#define OFF_RESID_SC (OFF_DP      + NB * H2)
#define OFF_RESID    (OFF_RESID_SC+ NB * H2)
#define OFF_RESID2   (OFF_RESID   + NB * H2)
#define OFF_DECIN    (OFF_RESID2  + NB * H2)
#define OFF_SSUM     (OFF_DECIN   + NB * H4)
#define OFF_FLAGS    (OFF_SSUM    + 64)     // 48 ints (slice flags)
#define OFF_HATT     (OFF_FLAGS   + 64)
#define OFF_HD1      (OFF_HATT    + NB * H2)
#define OFF_HD2      (OFF_HD1     + NB * H2)
#define SCRATCH_TOTAL (OFF_HD2    + NB * H2)

__device__ __align__(256) float g_scratch[SCRATCH_TOTAL];
__device__ unsigned g_bar[16];   // monotonic epoch barriers (never reset)

// ---------------------------------------------------------------------------
// Math helpers
// ---------------------------------------------------------------------------
__device__ __forceinline__ float fast_tanh(float x) {
    float e = __expf(2.0f * x);
    return 1.0f - 2.0f / (e + 1.0f);
}
__device__ __forceinline__ float approx_tanh(float x) {
    float y;
    asm("tanh.approx.f32 %0, %1;" : "=f"(y) : "f"(x));
    return y;
}
__device__ __forceinline__ float fast_sigmoid(float x) {
    return 1.0f / (1.0f + __expf(-x));
}
__device__ __forceinline__ ull pk2(float x, float y) {
    ull r;
    asm("mov.b64 %0, {%1, %2};" : "=l"(r) : "f"(x), "f"(y));
    return r;
}
__device__ __forceinline__ void upk2(ull v, float& x, float& y) {
    asm("mov.b64 {%0, %1}, %2;" : "=f"(x), "=f"(y) : "l"(v));
}
__device__ __forceinline__ void ffma2(ull& d, ull a, ull b) {
    asm("fma.rn.f32x2 %0, %1, %2, %0;" : "+l"(d) : "l"(a), "l"(b));
}
__device__ __forceinline__ void red4(float* p, float x, float y, float z, float w) {
    asm volatile("red.global.add.v4.f32 [%0], {%1,%2,%3,%4};"
                 :: "l"(p), "f"(x), "f"(y), "f"(z), "f"(w) : "memory");
}

// ---------------------------------------------------------------------------
// Device-wide barrier (monotonic epoch; all NGRID CTAs co-resident)
// ---------------------------------------------------------------------------
__device__ __forceinline__ void gsync(int id) {
    __syncthreads();
    if (threadIdx.x == 0) {
        unsigned* p = &g_bar[id];
        unsigned old;
        asm volatile("atom.release.gpu.add.u32 %0, [%1], 1;"
                     : "=r"(old) : "l"(p) : "memory");
        unsigned target = (old / NGRID) * NGRID + NGRID;
        unsigned cur;
        do {
            asm volatile("ld.acquire.gpu.u32 %0, [%1];"
                         : "=r"(cur) : "l"(p) : "memory");
            if (cur >= target) break;
            __nanosleep(32);
        } while (true);
    }
    __syncthreads();
}

// ---------------------------------------------------------------------------
// Kernel parameters
// ---------------------------------------------------------------------------
struct KParams {
    const float *input_enc, *attW_enc, *input_dec;
    const int* lengths;
    const float *hidden_att, *hidden_dec1, *hidden_dec2;
    const float *W_pre1, *b_pre1, *W_pre2, *b_pre2;
    const float *Wih_att, *Whh_att, *bih_att, *bhh_att;
    const float *W_ld, *b_ld, *W_attn, *b_attn, *W_sc, *b_sc;
    const float *Wih_d1, *Whh_d1, *bih_d1, *bhh_d1;
    const float *Wih_d2, *Whh_d2, *bih_d2, *bhh_d2;
    const float *W_out, *b_out;
    float *out, *h_att_out, *h_d1_out, *h_d2_out;
};

// ---------------------------------------------------------------------------
// GEMM descriptor (64x64 tile, 128 threads, split-K, red.v4 epilogue)
// mode: 0 identity, 1 relu(A), 2 divide cols k<1024 by ssum[row]
// ---------------------------------------------------------------------------
struct GD {
    const float* A; const float* W; float* C;
    const float* ssum; const int* slices;
    int lda, M, K, KS, inner, mode, nCol, start, nBlocks;
};

__device__ __forceinline__ GD mk(const float* A, int lda, int mode, const float* W,
                                 float* C, int M, int K, int KS, int inner,
                                 const float* ssum, const int* slices) {
    GD d;
    d.A = A; d.W = W; d.C = C; d.ssum = ssum; d.slices = slices;
    d.lda = lda; d.M = M; d.K = K; d.KS = KS; d.inner = inner; d.mode = mode;
    d.nCol = (M + 63) >> 6; d.start = 0; d.nBlocks = d.nCol * (K / KS);
    return d;
}

__device__ __noinline__ void gemm_stage(const GD* P, int n, float* As, float* Ws) {
    int total = P[n - 1].start + P[n - 1].nBlocks;
    int tid = threadIdx.x;
    int ty = tid >> 4;
    int tx = tid & 15;
    int arow = tid & 63;
    int half = tid >> 6;
    int wcol = tid & 63;
    const float4 z4 = make_float4(0.f, 0.f, 0.f, 0.f);

    for (int b = blockIdx.x; b < total; b += NGRID) {
        GD d = P[0];
        for (int i = 1; i < n; i++)
            if (b >= P[i].start) d = P[i];
        if (d.slices) {
            int s = 0;
#pragma unroll
            for (int i = 0; i < 16; i++) s |= d.slices[i];
            if (s == 0) continue;
        }
        int lb = b - d.start;
        int colBlock = lb % d.nCol;
        int kBlock = lb / d.nCol;
        int colBase = colBlock * 64;
        int k0 = kBlock * d.KS;
        int gc = colBase + wcol;
        bool wvalid = (gc < d.M);

        float wv = 1.0f;
        if (d.mode == 2) wv = 1.0f / fmaxf(d.ssum[arow], 1e-12f);

        const float* aptr = d.A + (size_t)arow * d.lda;
        const float* wptr = d.W + (size_t)(wvalid ? gc : 0) * d.K;

        ull acc[4][4];
#pragma unroll
        for (int p = 0; p < 4; p++)
#pragma unroll
            for (int j = 0; j < 4; j++) acc[p][j] = pk2(0.0f, 0.0f);

        int nref = d.KS / d.inner;
        int hk = d.inner >> 1;
        int nf4 = hk >> 2;

        float4 aq[4], wq[4];
#pragma unroll
        for (int q = 0; q < 4; q++) {
            if (q < nf4) {
                int kl = half * hk + q * 4;
                aq[q] = *(const float4*)(aptr + k0 + kl);
                wq[q] = wvalid ? *(const float4*)(wptr + k0 + kl) : z4;
            }
        }

        int kb = k0;
        for (int rf = 0; rf < nref; rf++) {
#pragma unroll
            for (int q = 0; q < 4; q++) {
                if (q < nf4) {
                    int kl = half * hk + q * 4;
                    float4 v = aq[q];
                    if (d.mode == 1) {
                        v.x = fmaxf(v.x, 0.f); v.y = fmaxf(v.y, 0.f);
                        v.z = fmaxf(v.z, 0.f); v.w = fmaxf(v.w, 0.f);
                    } else if (d.mode == 2 && (kb + kl) < H2) {
                        v.x *= wv; v.y *= wv; v.z *= wv; v.w *= wv;
                    }
                    As[(kl + 0) * 64 + arow] = v.x; As[(kl + 1) * 64 + arow] = v.y;
                    As[(kl + 2) * 64 + arow] = v.z; As[(kl + 3) * 64 + arow] = v.w;
                    float4 u = wq[q];
                    Ws[(kl + 0) * 64 + wcol] = u.x; Ws[(kl + 1) * 64 + wcol] = u.y;
                    Ws[(kl + 2) * 64 + wcol] = u.z; Ws[(kl + 3) * 64 + wcol] = u.w;
                }
            }
            __syncthreads();

            if (rf + 1 < nref) {
                int kn = kb + d.inner;
#pragma unroll
                for (int q = 0; q < 4; q++) {
                    if (q < nf4) {
                        int kl = half * hk + q * 4;
                        aq[q] = *(const float4*)(aptr + kn + kl);
                        wq[q] = wvalid ? *(const float4*)(wptr + kn + kl) : z4;
                    }
                }
            }

#pragma unroll 4
            for (int kk = 0; kk < d.inner; kk++) {
                const float* ab = &As[kk * 64 + ty * 8];
                ulonglong2 Ap0 = *(const ulonglong2*)(ab);
                ulonglong2 Ap1 = *(const ulonglong2*)(ab + 4);
                float4 bv = *(const float4*)&Ws[kk * 64 + tx * 4];
                ull b0 = pk2(bv.x, bv.x);
                ull b1 = pk2(bv.y, bv.y);
                ull b2 = pk2(bv.z, bv.z);
                ull b3 = pk2(bv.w, bv.w);
                ffma2(acc[0][0], Ap0.x, b0); ffma2(acc[0][1], Ap0.x, b1);
                ffma2(acc[0][2], Ap0.x, b2); ffma2(acc[0][3], Ap0.x, b3);
                ffma2(acc[1][0], Ap0.y, b0); ffma2(acc[1][1], Ap0.y, b1);
                ffma2(acc[1][2], Ap0.y, b2); ffma2(acc[1][3], Ap0.y, b3);
                ffma2(acc[2][0], Ap1.x, b0); ffma2(acc[2][1], Ap1.x, b1);
                ffma2(acc[2][2], Ap1.x, b2); ffma2(acc[2][3], Ap1.x, b3);
                ffma2(acc[3][0], Ap1.y, b0); ffma2(acc[3][1], Ap1.y, b1);
                ffma2(acc[3][2], Ap1.y, b2); ffma2(acc[3][3], Ap1.y, b3);
            }
            __syncthreads();
            kb += d.inner;
        }

        int col = colBase + tx * 4;
        if (col < d.M) {
#pragma unroll
            for (int p = 0; p < 4; p++) {
                int r0 = ty * 8 + 2 * p;
                float lo0, hi0, lo1, hi1, lo2, hi2, lo3, hi3;
                upk2(acc[p][0], lo0, hi0);
                upk2(acc[p][1], lo1, hi1);
                upk2(acc[p][2], lo2, hi2);
                upk2(acc[p][3], lo3, hi3);
                red4(&d.C[(size_t)r0 * d.M + col], lo0, lo1, lo2, lo3);
                red4(&d.C[(size_t)(r0 + 1) * d.M + col], hi0, hi1, hi2, hi3);
            }
        }
    }
}

// ---------------------------------------------------------------------------
// GRU combine (grid-stride)
// ---------------------------------------------------------------------------
__device__ __noinline__ void combine_stage(const float* gi, const float* gh,
        const float* bih, const float* bhh, const float* hprev,
        float* hout, const float* extra_in, float* extra_out, int mode) {
    for (int idx = blockIdx.x * NT + threadIdx.x; idx < NB * H2; idx += NGRID * NT) {
        int n = idx >> 10;
        int j = idx & (H2 - 1);
        const float* gin = gi + (size_t)n * H3;
        const float* ghn = gh + (size_t)n * H3;
        float ir = gin[j]           + bih[j];
        float iz = gin[j + H2]      + bih[j + H2];
        float in_ = gin[j + 2 * H2] + bih[j + 2 * H2];
        float hr = ghn[j]           + bhh[j];
        float hz = ghn[j + H2]      + bhh[j + H2];
        float hn = ghn[j + 2 * H2]  + bhh[j + 2 * H2];
        float r = fast_sigmoid(ir + hr);
        float z = fast_sigmoid(iz + hz);
        float nn = fast_tanh(in_ + r * hn);
        float h = (1.0f - z) * nn + z * hprev[idx];
        hout[idx] = h;
        if (mode == 1) {
            extra_out[(size_t)n * H4 + H2 + j] = h;
        } else if (mode == 2) {
            extra_out[idx] = extra_in[idx] + h;
        }
    }
}

// ---------------------------------------------------------------------------
// Init stage: flag slices + zeroing + bias broadcasts
// ---------------------------------------------------------------------------
__device__ __noinline__ void init_stage(const KParams& p) {
    if (blockIdx.x < 48) {
        int buf = blockIdx.x >> 4, s = blockIdx.x & 15;
        const float* hsrc = (buf == 0) ? p.hidden_att
                          : (buf == 1) ? p.hidden_dec1 : p.hidden_dec2;
        const float* base = hsrc + s * 4096;
        int any = 0;
        for (int i = threadIdx.x; i < 4096; i += NT) any |= (base[i] != 0.0f);
        int r = __syncthreads_or(any);
        if (threadIdx.x == 0)
            ((int*)(g_scratch + OFF_FLAGS))[blockIdx.x] = r;
    }
    int gtid = blockIdx.x * NT + threadIdx.x;
    float4 z4 = make_float4(0.f, 0.f, 0.f, 0.f);
    float4* g4 = (float4*)g_scratch;
    for (int i = gtid; i < (6 * GSZ) / 4; i += NGRID * NT) g4[i] = z4;
    for (int i = gtid; i < NB * H2; i += NGRID * NT) {
        int j = i & (H2 - 1);
        g_scratch[OFF_PRE_A + i]    = p.b_pre1[j];
        g_scratch[OFF_DP + i]       = p.b_ld[j];
        g_scratch[OFF_RESID_SC + i] = p.b_sc[j];
        int n = i >> 10;
        g_scratch[OFF_DECIN + (size_t)n * H4 + j] = 0.0f;
    }
    for (int i = gtid; i < NB * HH; i += NGRID * NT)
        g_scratch[OFF_PRE + i] = p.b_pre2[i & (HH - 1)];
    for (int i = gtid; i < NB * RR * OO; i += NGRID * NT)
        p.out[i] = p.b_out[i % (RR * OO)];
    if (gtid < 64) g_scratch[OFF_SSUM + gtid] = 0.0f;
}

// ---------------------------------------------------------------------------
// Persistent kernel A: init .. dec_proj
// ---------------------------------------------------------------------------
__global__ __launch_bounds__(NT, 4) void mega_a_kernel(KParams p) {
    __shared__ float sbuf[4096];
    float* As = sbuf;
    float* Ws = sbuf + 2048;

    float* gi_att = g_scratch + OFF_GI_ATT;
    float* gh_att = g_scratch + OFF_GH_ATT;
    float* gh_d1  = g_scratch + OFF_GH_D1;
    float* gh_d2  = g_scratch + OFF_GH_D2;
    float* pre_a  = g_scratch + OFF_PRE_A;
    float* pre    = g_scratch + OFF_PRE;
    float* dp     = g_scratch + OFF_DP;
    float* dec_in = g_scratch + OFF_DECIN;
    const int* fl = (const int*)(g_scratch + OFF_FLAGS);

    init_stage(p);
    gsync(0);

    {
        GD ds[4] = {
            mk(p.input_dec,   OO, 0, p.W_pre1,  pre_a,  H2, OO,   16, 16, 0, 0),
            mk(p.hidden_att,  H2, 0, p.Whh_att, gh_att, H3, H2,  256, 32, 0, fl + 0),
            mk(p.hidden_dec1, H2, 0, p.Whh_d1,  gh_d1,  H3, H2,  256, 32, 0, fl + 16),
            mk(p.hidden_dec2, H2, 0, p.Whh_d2,  gh_d2,  H3, H2,  256, 32, 0, fl + 32),
        };
        int st = 0;
        for (int i = 0; i < 4; i++) { ds[i].start = st; st += ds[i].nBlocks; }
        gemm_stage(ds, 4, As, Ws);
    }
    gsync(1);

    {
        GD ds[1] = { mk(pre_a, H2, 1, p.W_pre2, pre, HH, H2, 32, 32, 0, 0) };
        gemm_stage(ds, 1, As, Ws);
    }
    gsync(2);

    {
        GD ds[1] = { mk(pre, HH, 1, p.Wih_att, gi_att, H3, HH, 64, 32, 0, 0) };
        gemm_stage(ds, 1, As, Ws);
    }
    gsync(3);

    combine_stage(gi_att, gh_att, p.bih_att, p.bhh_att, p.hidden_att,
                  p.h_att_out, 0, dec_in, 1);
    gsync(4);

    {
        GD ds[1] = { mk(p.h_att_out, H2, 0, p.W_ld, dp, H2, H2, 64, 32, 0, 0) };
        gemm_stage(ds, 1, As, Ws);
    }
}

// ---------------------------------------------------------------------------
// Wide attention kernel (round-7 style): per (n, 32-t chunk) 256-thread block
// ---------------------------------------------------------------------------
__global__ void __launch_bounds__(256) attn_fused_kernel(
    const float* __restrict__ attW, const float* __restrict__ enc,
    const float* __restrict__ dp, const float* __restrict__ Wattn,
    const float* __restrict__ battn, const int* __restrict__ lengths,
    float* __restrict__ dec_in, float* __restrict__ ssum) {
    __shared__ float dps[H2];
    __shared__ float was[H2];
    __shared__ float ss[CH];
    int n = blockIdx.y;
    int t0 = blockIdx.x * CH;
    int len = lengths[n];
    if (t0 >= len) return;
    int kmax = min(CH, len - t0);
    int tid = threadIdx.x;

    for (int i = tid; i < H2; i += 256) {
        dps[i] = dp[(size_t)n * H2 + i];
        was[i] = Wattn[i];
    }
    if (tid < CH) ss[tid] = 0.0f;
    __syncthreads();

    int warp = tid >> 5, lane = tid & 31;
    float bb = battn[0];
#pragma unroll
    for (int rep = 0; rep < CH / 8; rep++) {
        int lt = warp + rep * 8;
        if (lt < kmax) {
            const float4* row = (const float4*)(attW + ((size_t)n * TT + t0 + lt) * H2);
            const float4* d4p = (const float4*)dps;
            const float4* w4p = (const float4*)was;
            float s = 0.0f;
#pragma unroll
            for (int it = 0; it < 8; it++) {
                int i = it * 32 + lane;
                float4 v = row[i];
                float4 dd = d4p[i];
                float4 ww = w4p[i];
                s += approx_tanh(v.x + dd.x) * ww.x
                   + approx_tanh(v.y + dd.y) * ww.y
                   + approx_tanh(v.z + dd.z) * ww.z
                   + approx_tanh(v.w + dd.w) * ww.w;
            }
#pragma unroll
            for (int o = 16; o; o >>= 1) s += __shfl_xor_sync(0xffffffffu, s, o);
            if (lane == 0) ss[lt] = __expf(s + bb);
        }
    }
    __syncthreads();

    if (warp == 0) {
        float v = (lane < CH) ? ss[lane] : 0.0f;
#pragma unroll
        for (int o = 16; o; o >>= 1) v += __shfl_xor_sync(0xffffffffu, v, o);
        if (lane == 0) atomicAdd(&ssum[n], v);
    }

    int h = tid * 4;
    const float* ebase = enc + (size_t)n * TT * H2 + (size_t)t0 * H2 + h;
    float ax = 0.f, ay = 0.f, az = 0.f, aw = 0.f;
#pragma unroll 4
    for (int t = 0; t < kmax; t++) {
        float w = ss[t];
        float4 e = *(const float4*)(ebase + (size_t)t * H2);
        ax += w * e.x; ay += w * e.y; az += w * e.z; aw += w * e.w;
    }
    red4(&dec_in[(size_t)n * H4 + h], ax, ay, az, aw);
}

// ---------------------------------------------------------------------------
// Persistent kernel B: short-cut .. output projection
// ---------------------------------------------------------------------------
__global__ __launch_bounds__(NT, 4) void mega_b_kernel(KParams p) {
    __shared__ float sbuf[4096];
    float* As = sbuf;
    float* Ws = sbuf + 2048;

    float* gi_d1  = g_scratch + OFF_GI_D1;
    float* gh_d1  = g_scratch + OFF_GH_D1;
    float* gi_d2  = g_scratch + OFF_GI_D2;
    float* gh_d2  = g_scratch + OFF_GH_D2;
    float* resid_sc = g_scratch + OFF_RESID_SC;
    float* resid  = g_scratch + OFF_RESID;
    float* resid2 = g_scratch + OFF_RESID2;
    float* dec_in = g_scratch + OFF_DECIN;
    float* ssum   = g_scratch + OFF_SSUM;

    {
        GD ds[2] = {
            mk(dec_in, H4, 2, p.W_sc,   resid_sc, H2, H4, 128, 32, ssum, 0),
            mk(dec_in, H4, 2, p.Wih_d1, gi_d1,    H3, H4, 128, 32, ssum, 0),
        };
        int st = 0;
        for (int i = 0; i < 2; i++) { ds[i].start = st; st += ds[i].nBlocks; }
        gemm_stage(ds, 2, As, Ws);
    }
    gsync(8);

    combine_stage(gi_d1, gh_d1, p.bih_d1, p.bhh_d1, p.hidden_dec1,
                  p.h_d1_out, resid_sc, resid, 2);
    gsync(9);

    {
        GD ds[1] = { mk(resid, H2, 0, p.Wih_d2, gi_d2, H3, H2, 128, 32, 0, 0) };
        gemm_stage(ds, 1, As, Ws);
    }
    gsync(10);

    combine_stage(gi_d2, gh_d2, p.bih_d2, p.bhh_d2, p.hidden_dec2,
                  p.h_d2_out, resid, resid2, 2);
    gsync(11);

    {
        GD ds[1] = { mk(resid2, H2, 0, p.W_out, p.out, RR * OO, H2, 16, 16, 0, 0) };
        gemm_stage(ds, 1, As, Ws);
    }
}

// ---------------------------------------------------------------------------
// Host launch: THREE kernels
// ---------------------------------------------------------------------------
extern "C" void kernel_launch(void* const* d_in, const int* in_sizes, int n_in,
                              void* d_out, int out_size) {
    KParams p;
    p.input_enc   = (const float*)d_in[0];
    p.attW_enc    = (const float*)d_in[1];
    p.input_dec   = (const float*)d_in[2];
    p.lengths     = (const int*)  d_in[3];
    p.hidden_att  = (const float*)d_in[4];
    p.hidden_dec1 = (const float*)d_in[5];
    p.hidden_dec2 = (const float*)d_in[6];
    p.W_pre1 = (const float*)d_in[7];   p.b_pre1 = (const float*)d_in[8];
    p.W_pre2 = (const float*)d_in[9];   p.b_pre2 = (const float*)d_in[10];
    p.Wih_att = (const float*)d_in[11]; p.Whh_att = (const float*)d_in[12];
    p.bih_att = (const float*)d_in[13]; p.bhh_att = (const float*)d_in[14];
    p.W_ld  = (const float*)d_in[15];   p.b_ld  = (const float*)d_in[16];
    p.W_attn = (const float*)d_in[17];  p.b_attn = (const float*)d_in[18];
    p.W_sc  = (const float*)d_in[19];   p.b_sc  = (const float*)d_in[20];
    p.Wih_d1 = (const float*)d_in[21];  p.Whh_d1 = (const float*)d_in[22];
    p.bih_d1 = (const float*)d_in[23];  p.bhh_d1 = (const float*)d_in[24];
    p.Wih_d2 = (const float*)d_in[25];  p.Whh_d2 = (const float*)d_in[26];
    p.bih_d2 = (const float*)d_in[27];  p.bhh_d2 = (const float*)d_in[28];
    p.W_out = (const float*)d_in[29];   p.b_out = (const float*)d_in[30];

    float* out = (float*)d_out;
    p.out = out;

    float* sc = nullptr;
    cudaGetSymbolAddress((void**)&sc, g_scratch);

    bool full_out = (out_size >= NB * RR * OO + 3 * NB * H2);
    p.h_att_out = full_out ? out + NB * RR * OO : sc + OFF_HATT;
    p.h_d1_out  = full_out ? p.h_att_out + NB * H2 : sc + OFF_HD1;
    p.h_d2_out  = full_out ? p.h_d1_out + NB * H2 : sc + OFF_HD2;

    mega_a_kernel<<<NGRID, NT>>>(p);
    attn_fused_kernel<<<dim3(NCHUNK, NB), 256>>>(p.attW_enc, p.input_enc,
                                                 sc + OFF_DP, p.W_attn, p.b_attn,
                                                 p.lengths, sc + OFF_DECIN,
                                                 sc + OFF_SSUM);
    mega_b_kernel<<<NGRID, NT>>>(p);
}